// round 8
// baseline (speedup 1.0000x reference)
#include <cuda_runtime.h>
#include <cstdint>

// ---------------- problem constants ----------------
#define B_    4
#define C_    64
#define NPIX  1024            // 32*32
#define NB    (B_ * C_ * NPIX)
#define PR    34              // padded rows used (0..33)
#define PSTR  36              // padded row stride in g_a (floats)
#define PLANE (PR * PSTR)     // floats per (b,c) plane
#define S_    8               // K-split factor
#define CCHUNK 8              // channels per split
#define ASTRIDE 40            // As row stride (floats)
#define KW_   72              // k-steps per split (CCHUNK*9)
#define NPAD  (200 * B_ * C_) // padding elements across all planes

// ---------------- scratch (device globals) ----------------
__device__ float g_a1[B_ * C_ * PLANE];          // relu(bn1(x)), zero-padded
__device__ float g_a2[B_ * C_ * PLANE];          // relu(bn2(adder1)), zero-padded
__device__ float g_p1[S_ * NB];                  // adder1 partials (TRUE values)
__device__ float g_p2[S_ * NB];                  // adder2 partials (TRUE values)
__device__ float g_out2[NB];                     // adder2 full output
__device__ float g_s[B_ * C_];                   // channel means
__device__ __align__(16) float g_wr[2 * S_ * KW_ * 64];  // reordered weights

// ---------------- weight reorder: w[(o*C+c0+cc)*9+t9] -> [st][sp][k][o] ---
__global__ void k_wprep(const float* __restrict__ w1,
                        const float* __restrict__ w2) {
    int idx = blockIdx.x * blockDim.x + threadIdx.x;
    if (idx >= 2 * S_ * KW_ * 64) return;
    int o  = idx & 63;
    int t  = idx >> 6;
    int k  = t % KW_;
    int sp = (t / KW_) % S_;
    int st = t / (KW_ * S_);
    int cc = k / 9;
    int t9 = k - cc * 9;
    const float* w = st ? w2 : w1;
    g_wr[idx] = w[(o * C_ + sp * CCHUNK + cc) * 9 + t9];
}

// ---------------- BN + ReLU into zero-padded layout (vectorized) ---------
// interior quads: float4 partial reads; pad elements zeroed by tail range
__global__ void k_bnpad(const float* __restrict__ xin, int stage,
                        const float* __restrict__ gam,
                        const float* __restrict__ bet,
                        const float* __restrict__ mu,
                        const float* __restrict__ var) {
    int idx = blockIdx.x * blockDim.x + threadIdx.x;
    const int NQ = B_ * C_ * 256;            // interior quads
    float* outp = stage ? g_a2 : g_a1;

    if (idx < NQ) {
        int bc   = idx >> 8;
        int quad = idx & 255;
        int r    = quad >> 3;                // 0..31
        int qx   = (quad & 7) * 4;           // 0,4,...,28
        int pix0 = bc * NPIX + r * 32 + qx;

        float4 s;
        if (stage) {
            s = make_float4(0.f, 0.f, 0.f, 0.f);
#pragma unroll
            for (int sp = 0; sp < S_; sp++) {
                float4 p = *(const float4*)&g_p1[sp * NB + pix0];
                s.x += p.x; s.y += p.y; s.z += p.z; s.w += p.w;
            }
        } else {
            s = *(const float4*)&xin[pix0];
        }
        int c = bc & (C_ - 1);
        float inv  = gam[c] * rsqrtf(var[c] + 1e-5f);
        float bias = bet[c] - mu[c] * inv;
        float* ob = outp + bc * PLANE + (r + 1) * PSTR + qx + 1;
        ob[0] = fmaxf(s.x * inv + bias, 0.f);
        ob[1] = fmaxf(s.y * inv + bias, 0.f);
        ob[2] = fmaxf(s.z * inv + bias, 0.f);
        ob[3] = fmaxf(s.w * inv + bias, 0.f);
    } else if (idx < NQ + NPAD) {
        int j  = idx - NQ;
        int bc = j / 200;
        int p  = j - bc * 200;
        int r, q;
        if (p < 36)      { r = 0;  q = p; }
        else if (p < 72) { r = 33; q = p - 36; }
        else {
            int t = p - 72;
            r = 1 + (t >> 2);
            int qi = t & 3;
            q = qi ? 32 + qi : 0;            // cols 0,33,34,35
        }
        outp[bc * PLANE + r * PSTR + q] = 0.f;
    }
}

// ---------------- AdderNet conv via min-identity, K-split ----------------
// sum|a-w| = sumA + sumW - 2*sum min(a,w)
// grid: (64 pixel-tiles, 8 k-splits); block: 128 threads (4 warps)
// thread tile = 2 rows x 4 consecutive cols (x0=4*pcol0) x 4 out-ch
__global__ __launch_bounds__(128, 7) void k_adder(int stage) {
    __shared__ __align__(16) float As[CCHUNK * 4 * ASTRIDE];  // staged a, 5 KB
    __shared__ __align__(16) float Bs[KW_ * 64];              // weights, 18.4 KB
    __shared__ float Rs[CCHUNK * 4 * 32];                     // 3-tap row sums
    __shared__ float sAs[64];                                 // window sums per pixel
    __shared__ float sWs[64];                                 // weight sums per out-ch

    const float* apad = stage ? g_a2 : g_a1;
    float*       part = stage ? g_p2 : g_p1;

    int tid  = threadIdx.x;
    int bx   = blockIdx.x;           // 0..63
    int sp   = blockIdx.y;           // 0..7 (k-split)
    int b    = bx >> 4;
    int row0 = (bx & 15) * 2;        // output rows row0, row0+1
    int c0   = sp * CCHUNK;

    int og    = tid >> 3;            // 0..15 -> out channels og*4..og*4+3
    int pcol0 = tid & 7;             // 0..7
    int x0    = pcol0 * 4;           // 4 consecutive output cols, 16B aligned

    // stage A: 8 channels x 4 padded rows x ASTRIDE cols (zero-fill tail)
    const float* ap = apad + (b * C_ + c0) * PLANE;
    for (int i = tid; i < CCHUNK * 4 * ASTRIDE; i += 128) {
        int cc  = i / (4 * ASTRIDE);
        int rem = i - cc * (4 * ASTRIDE);
        int r   = rem / ASTRIDE;
        int q   = rem - r * ASTRIDE;
        As[i] = (q < PSTR) ? ap[cc * PLANE + (row0 + r) * PSTR + q] : 0.f;
    }
    // stage B: coalesced float4 copy from reordered weights
    {
        const float4* wr4 = (const float4*)(g_wr + (stage * S_ + sp) * KW_ * 64);
        float4* Bs4 = (float4*)Bs;
        for (int i = tid; i < KW_ * 16; i += 128)   // 72*64/4 = 1152
            Bs4[i] = wr4[i];
    }
    __syncthreads();

    // phase 1: horizontal 3-tap row sums + per-oc weight sums
    for (int i = tid; i < CCHUNK * 4 * 32; i += 128) {
        int cc = i >> 7;
        int rm = i & 127;
        int r  = rm >> 5;
        int x  = rm & 31;
        const float* p = &As[cc * (4 * ASTRIDE) + r * ASTRIDE + x];
        Rs[i] = p[0] + p[1] + p[2];
    }
    if (tid < 64) {
        float s = 0.f;
#pragma unroll
        for (int k = 0; k < KW_; k++) s += Bs[k * 64 + tid];
        sWs[tid] = s;
    }
    __syncthreads();

    // phase 2: vertical 3-tap + channel sum -> per-pixel window sums
    if (tid < 64) {
        int y = tid >> 5, x = tid & 31;
        float s = 0.f;
#pragma unroll
        for (int cc = 0; cc < CCHUNK; cc++)
#pragma unroll
            for (int kh = 0; kh < 3; kh++)
                s += Rs[cc * 128 + (y + kh) * 32 + x];
        sAs[tid] = s;
    }
    __syncthreads();

    float acc[2][4][4];   // [prow][cidx][oc]
#pragma unroll
    for (int p = 0; p < 2; p++)
#pragma unroll
        for (int c = 0; c < 4; c++)
#pragma unroll
            for (int j = 0; j < 4; j++) acc[p][c][j] = 0.f;

#pragma unroll 1
    for (int cc = 0; cc < CCHUNK; ++cc) {
        const float* base = &As[cc * (4 * ASTRIDE)];
        float rows[4][6];   // rolling register window of activation rows
#pragma unroll
        for (int r = 0; r < 2; r++) {
            float4 q4 = *(const float4*)(base + r * ASTRIDE + x0);
            float2 q2 = *(const float2*)(base + r * ASTRIDE + x0 + 4);
            rows[r][0] = q4.x; rows[r][1] = q4.y; rows[r][2] = q4.z;
            rows[r][3] = q4.w; rows[r][4] = q2.x; rows[r][5] = q2.y;
        }
#pragma unroll
        for (int kh = 0; kh < 3; ++kh) {
            if (kh < 2) {   // prefetch row kh+2 before this kh's math
                int r = kh + 2;
                float4 q4 = *(const float4*)(base + r * ASTRIDE + x0);
                float2 q2 = *(const float2*)(base + r * ASTRIDE + x0 + 4);
                rows[r][0] = q4.x; rows[r][1] = q4.y; rows[r][2] = q4.z;
                rows[r][3] = q4.w; rows[r][4] = q2.x; rows[r][5] = q2.y;
            }
#pragma unroll
            for (int kw = 0; kw < 3; ++kw) {
                float4 bq = *(const float4*)&Bs[(cc * 9 + kh * 3 + kw) * 64 + og * 4];
                float bv[4] = {bq.x, bq.y, bq.z, bq.w};
#pragma unroll
                for (int pr = 0; pr < 2; pr++) {
#pragma unroll
                    for (int c = 0; c < 4; c++) {
                        float a = rows[pr + kh][c + kw];
#pragma unroll
                        for (int j = 0; j < 4; j++)
                            acc[pr][c][j] += fminf(a, bv[j]);  // FMNMX + FADD
                    }
                }
            }
        }
    }

    // epilogue: true partial = 2*summin - sumA - sumW ; STG.128 per (oc,row)
    float sw[4];
#pragma unroll
    for (int j = 0; j < 4; j++) sw[j] = sWs[og * 4 + j];
    float sa[2][4];
#pragma unroll
    for (int pr = 0; pr < 2; pr++)
#pragma unroll
        for (int c = 0; c < 4; c++) sa[pr][c] = sAs[pr * 32 + x0 + c];

    float* pbase = part + ((sp * B_ + b) * C_ + og * 4) * NPIX;
#pragma unroll
    for (int j = 0; j < 4; j++) {
#pragma unroll
        for (int pr = 0; pr < 2; pr++) {
            int y = row0 + pr;
            float4 v;
            v.x = fmaf(2.f, acc[pr][0][j], -sa[pr][0]) - sw[j];
            v.y = fmaf(2.f, acc[pr][1][j], -sa[pr][1]) - sw[j];
            v.z = fmaf(2.f, acc[pr][2][j], -sa[pr][2]) - sw[j];
            v.w = fmaf(2.f, acc[pr][3][j], -sa[pr][3]) - sw[j];
            *(float4*)&pbase[j * NPIX + y * 32 + x0] = v;
        }
    }
}

// ---------------- combine adder2 partials + channel means (vectorized) ---
__global__ void k_comb_se() {
    int bc  = blockIdx.x;   // 0..255 = b*64 + c
    int tid = threadIdx.x;  // 256 -> one quad each
    int pix0 = bc * NPIX + tid * 4;

    float4 v = make_float4(0.f, 0.f, 0.f, 0.f);
#pragma unroll
    for (int sp = 0; sp < S_; sp++) {
        float4 p = *(const float4*)&g_p2[sp * NB + pix0];
        v.x += p.x; v.y += p.y; v.z += p.z; v.w += p.w;
    }
    *(float4*)&g_out2[pix0] = v;
    float lsum = v.x + v.y + v.z + v.w;

#pragma unroll
    for (int off = 16; off; off >>= 1)
        lsum += __shfl_xor_sync(0xffffffffu, lsum, off);
    __shared__ float ws[8];
    if ((tid & 31) == 0) ws[tid >> 5] = lsum;
    __syncthreads();
    if (tid == 0) {
        float t = 0.f;
#pragma unroll
        for (int i = 0; i < 8; i++) t += ws[i];
        g_s[bc] = t * (1.f / 1024.f);
    }
}

// ---------------- final: SE gate (per-block) + out = out2*g + x ----------
__global__ void k_final(const float* __restrict__ x,
                        const float* __restrict__ f1w, const float* __restrict__ f1b,
                        const float* __restrict__ f2w, const float* __restrict__ f2b,
                        float* __restrict__ out) {
    int bc  = blockIdx.x;            // 0..255 = b*64 + c
    int b   = bc >> 6;
    int c   = bc & 63;
    int tid = threadIdx.x;           // 256

    __shared__ float sh[64];
    __shared__ float gg;
    if (tid < 64) sh[tid] = g_s[b * 64 + tid];
    __syncthreads();
    if (tid == 0) {
        float h[4];
#pragma unroll
        for (int j = 0; j < 4; j++) {
            float a = f1b[j];
            for (int c2 = 0; c2 < 64; c2++) a += sh[c2] * f1w[j * 64 + c2];
            h[j] = fmaxf(a, 0.f);
        }
        float z = f2b[c];
#pragma unroll
        for (int j = 0; j < 4; j++) z += h[j] * f2w[c * 4 + j];
        gg = 1.f / (1.f + expf(-z));
    }
    __syncthreads();
    float g = gg;
    int pix0 = bc * NPIX + tid * 4;
    float4 o2 = *(const float4*)&g_out2[pix0];
    float4 xs = *(const float4*)&x[pix0];
    float4 r;
    r.x = o2.x * g + xs.x; r.y = o2.y * g + xs.y;
    r.z = o2.z * g + xs.z; r.w = o2.w * g + xs.w;
    *(float4*)&out[pix0] = r;
}

extern "C" void kernel_launch(void* const* d_in, const int* in_sizes, int n_in,
                              void* d_out, int out_size) {
    const float* x     = (const float*)d_in[0];
    const float* bn1_g = (const float*)d_in[1];
    const float* bn1_b = (const float*)d_in[2];
    const float* bn1_m = (const float*)d_in[3];
    const float* bn1_v = (const float*)d_in[4];
    const float* w1    = (const float*)d_in[5];
    const float* bn2_g = (const float*)d_in[6];
    const float* bn2_b = (const float*)d_in[7];
    const float* bn2_m = (const float*)d_in[8];
    const float* bn2_v = (const float*)d_in[9];
    const float* w2    = (const float*)d_in[10];
    const float* fc1_w = (const float*)d_in[11];
    const float* fc1_b = (const float*)d_in[12];
    const float* fc2_w = (const float*)d_in[13];
    const float* fc2_b = (const float*)d_in[14];
    float* out = (float*)d_out;

    const int wtot   = 2 * S_ * KW_ * 64;
    const int bn_tot = B_ * C_ * 256 + NPAD;
    dim3 ag(64, S_);

    k_wprep<<<(wtot + 255) / 256, 256>>>(w1, w2);
    k_bnpad<<<(bn_tot + 255) / 256, 256>>>(x, 0, bn1_g, bn1_b, bn1_m, bn1_v);
    k_adder<<<ag, 128>>>(0);
    k_bnpad<<<(bn_tot + 255) / 256, 256>>>(nullptr, 1, bn2_g, bn2_b, bn2_m, bn2_v);
    k_adder<<<ag, 128>>>(1);
    k_comb_se<<<256, 256>>>();
    k_final<<<256, 256>>>(x, fc1_w, fc1_b, fc2_w, fc2_b, out);
}

// round 9
// speedup vs baseline: 1.1388x; 1.1388x over previous
#include <cuda_runtime.h>
#include <cstdint>

// ---------------- problem constants ----------------
#define B_    4
#define C_    64
#define NPIX  1024            // 32*32
#define NB    (B_ * C_ * NPIX)
#define PR    34              // padded rows used (0..33)
#define PSTR  36              // padded row stride in g_a (floats)
#define PLANE (PR * PSTR)     // floats per (b,c) plane
#define S_    16              // K-split factor
#define CCHUNK 4              // channels per split
#define ASTRIDE 40            // As row stride (floats)
#define KW_   36              // k-steps per split (CCHUNK*9)
#define NPAD  (200 * B_ * C_) // padding elements across all planes

// ---------------- scratch (device globals) ----------------
__device__ float g_a1[B_ * C_ * PLANE];          // relu(bn1(x)), zero-padded
__device__ float g_a2[B_ * C_ * PLANE];          // relu(bn2(adder1)), zero-padded
__device__ float g_p1[S_ * NB];                  // adder1 partials (TRUE values)
__device__ float g_p2[S_ * NB];                  // adder2 partials (TRUE values)
__device__ float g_out2[NB];                     // adder2 full output
__device__ float g_s[B_ * C_];                   // channel means
__device__ __align__(16) float g_wr[2 * S_ * KW_ * 64];  // reordered weights

// ---------------- weight reorder: w[(o*C+c0+cc)*9+t9] -> [st][sp][k][o] ---
__global__ void k_wprep(const float* __restrict__ w1,
                        const float* __restrict__ w2) {
    int idx = blockIdx.x * blockDim.x + threadIdx.x;
    if (idx >= 2 * S_ * KW_ * 64) return;
    int o  = idx & 63;
    int t  = idx >> 6;
    int k  = t % KW_;
    int sp = (t / KW_) % S_;
    int st = t / (KW_ * S_);
    int cc = k / 9;
    int t9 = k - cc * 9;
    const float* w = st ? w2 : w1;
    g_wr[idx] = w[(o * C_ + sp * CCHUNK + cc) * 9 + t9];
}

// ---------------- BN + ReLU into zero-padded layout (vectorized) ---------
// interior quads: float4 partial reads; pad elements zeroed by tail range
__global__ void k_bnpad(const float* __restrict__ xin, int stage,
                        const float* __restrict__ gam,
                        const float* __restrict__ bet,
                        const float* __restrict__ mu,
                        const float* __restrict__ var) {
    int idx = blockIdx.x * blockDim.x + threadIdx.x;
    const int NQ = B_ * C_ * 256;            // interior quads
    float* outp = stage ? g_a2 : g_a1;

    if (idx < NQ) {
        int bc   = idx >> 8;
        int quad = idx & 255;
        int r    = quad >> 3;                // 0..31
        int qx   = (quad & 7) * 4;           // 0,4,...,28
        int pix0 = bc * NPIX + r * 32 + qx;

        float4 s;
        if (stage) {
            s = make_float4(0.f, 0.f, 0.f, 0.f);
#pragma unroll
            for (int sp = 0; sp < S_; sp++) {
                float4 p = *(const float4*)&g_p1[sp * NB + pix0];
                s.x += p.x; s.y += p.y; s.z += p.z; s.w += p.w;
            }
        } else {
            s = *(const float4*)&xin[pix0];
        }
        int c = bc & (C_ - 1);
        float inv  = gam[c] * rsqrtf(var[c] + 1e-5f);
        float bias = bet[c] - mu[c] * inv;
        float* ob = outp + bc * PLANE + (r + 1) * PSTR + qx + 1;
        ob[0] = fmaxf(s.x * inv + bias, 0.f);
        ob[1] = fmaxf(s.y * inv + bias, 0.f);
        ob[2] = fmaxf(s.z * inv + bias, 0.f);
        ob[3] = fmaxf(s.w * inv + bias, 0.f);
    } else if (idx < NQ + NPAD) {
        int j  = idx - NQ;
        int bc = j / 200;
        int p  = j - bc * 200;
        int r, q;
        if (p < 36)      { r = 0;  q = p; }
        else if (p < 72) { r = 33; q = p - 36; }
        else {
            int t = p - 72;
            r = 1 + (t >> 2);
            int qi = t & 3;
            q = qi ? 32 + qi : 0;            // cols 0,33,34,35
        }
        outp[bc * PLANE + r * PSTR + q] = 0.f;
    }
}

// ---------------- AdderNet conv via min-identity, K-split ----------------
// sum|a-w| = sumA + sumW - 2*sum min(a,w)
// grid: (64 pixel-tiles, 16 k-splits); block: 128 threads (4 warps)
// thread tile = 2 rows x 4 consecutive cols (x0=4*pcol0) x 4 out-ch
__global__ __launch_bounds__(128, 7) void k_adder(int stage) {
    __shared__ __align__(16) float As[CCHUNK * 4 * ASTRIDE];  // staged a
    __shared__ __align__(16) float Bs[KW_ * 64];              // weights, 9 KB
    __shared__ float Rs[CCHUNK * 4 * 32];                     // 3-tap row sums
    __shared__ float sAs[64];                                 // window sums per pixel
    __shared__ float sWs[64];                                 // weight sums per out-ch

    const float* apad = stage ? g_a2 : g_a1;
    float*       part = stage ? g_p2 : g_p1;

    int tid  = threadIdx.x;
    int bx   = blockIdx.x;           // 0..63
    int sp   = blockIdx.y;           // 0..15 (k-split)
    int b    = bx >> 4;
    int row0 = (bx & 15) * 2;        // output rows row0, row0+1
    int c0   = sp * CCHUNK;

    int og    = tid >> 3;            // 0..15 -> out channels og*4..og*4+3
    int pcol0 = tid & 7;             // 0..7
    int x0    = pcol0 * 4;           // 4 consecutive output cols, 16B aligned

    // stage A: 4 channels x 4 padded rows x ASTRIDE cols (zero-fill tail)
    const float* ap = apad + (b * C_ + c0) * PLANE;
    for (int i = tid; i < CCHUNK * 4 * ASTRIDE; i += 128) {
        int cc  = i / (4 * ASTRIDE);
        int rem = i - cc * (4 * ASTRIDE);
        int r   = rem / ASTRIDE;
        int q   = rem - r * ASTRIDE;
        As[i] = (q < PSTR) ? ap[cc * PLANE + (row0 + r) * PSTR + q] : 0.f;
    }
    // stage B: coalesced float4 copy from reordered weights
    {
        const float4* wr4 = (const float4*)(g_wr + (stage * S_ + sp) * KW_ * 64);
        float4* Bs4 = (float4*)Bs;
        for (int i = tid; i < KW_ * 16; i += 128)   // 36*64/4 = 576
            Bs4[i] = wr4[i];
    }
    __syncthreads();

    // phase 1: horizontal 3-tap row sums + per-oc weight sums
    for (int i = tid; i < CCHUNK * 4 * 32; i += 128) {
        int cc = i >> 7;
        int rm = i & 127;
        int r  = rm >> 5;
        int x  = rm & 31;
        const float* p = &As[cc * (4 * ASTRIDE) + r * ASTRIDE + x];
        Rs[i] = p[0] + p[1] + p[2];
    }
    if (tid < 64) {
        float s = 0.f;
#pragma unroll
        for (int k = 0; k < KW_; k++) s += Bs[k * 64 + tid];
        sWs[tid] = s;
    }
    __syncthreads();

    // phase 2: vertical 3-tap + channel sum -> per-pixel window sums
    if (tid < 64) {
        int y = tid >> 5, x = tid & 31;
        float s = 0.f;
#pragma unroll
        for (int cc = 0; cc < CCHUNK; cc++)
#pragma unroll
            for (int kh = 0; kh < 3; kh++)
                s += Rs[cc * 128 + (y + kh) * 32 + x];
        sAs[tid] = s;
    }
    __syncthreads();

    float acc[2][4][4];   // [prow][cidx][oc]
#pragma unroll
    for (int p = 0; p < 2; p++)
#pragma unroll
        for (int c = 0; c < 4; c++)
#pragma unroll
            for (int j = 0; j < 4; j++) acc[p][c][j] = 0.f;

#pragma unroll 1
    for (int cc = 0; cc < CCHUNK; ++cc) {
        const float* base = &As[cc * (4 * ASTRIDE)];
        float rows[4][6];   // rolling register window of activation rows
#pragma unroll
        for (int r = 0; r < 2; r++) {
            float4 q4 = *(const float4*)(base + r * ASTRIDE + x0);
            float2 q2 = *(const float2*)(base + r * ASTRIDE + x0 + 4);
            rows[r][0] = q4.x; rows[r][1] = q4.y; rows[r][2] = q4.z;
            rows[r][3] = q4.w; rows[r][4] = q2.x; rows[r][5] = q2.y;
        }
#pragma unroll
        for (int kh = 0; kh < 3; ++kh) {
            if (kh < 2) {   // prefetch row kh+2 before this kh's math
                int r = kh + 2;
                float4 q4 = *(const float4*)(base + r * ASTRIDE + x0);
                float2 q2 = *(const float2*)(base + r * ASTRIDE + x0 + 4);
                rows[r][0] = q4.x; rows[r][1] = q4.y; rows[r][2] = q4.z;
                rows[r][3] = q4.w; rows[r][4] = q2.x; rows[r][5] = q2.y;
            }
#pragma unroll
            for (int kw = 0; kw < 3; ++kw) {
                float4 bq = *(const float4*)&Bs[(cc * 9 + kh * 3 + kw) * 64 + og * 4];
                float bv[4] = {bq.x, bq.y, bq.z, bq.w};
#pragma unroll
                for (int pr = 0; pr < 2; pr++) {
#pragma unroll
                    for (int c = 0; c < 4; c++) {
                        float a = rows[pr + kh][c + kw];
#pragma unroll
                        for (int j = 0; j < 4; j++)
                            acc[pr][c][j] += fminf(a, bv[j]);  // FMNMX + FADD
                    }
                }
            }
        }
    }

    // epilogue: true partial = 2*summin - sumA - sumW ; STG.128 per (oc,row)
    float sw[4];
#pragma unroll
    for (int j = 0; j < 4; j++) sw[j] = sWs[og * 4 + j];
    float sa[2][4];
#pragma unroll
    for (int pr = 0; pr < 2; pr++)
#pragma unroll
        for (int c = 0; c < 4; c++) sa[pr][c] = sAs[pr * 32 + x0 + c];

    float* pbase = part + ((sp * B_ + b) * C_ + og * 4) * NPIX;
#pragma unroll
    for (int j = 0; j < 4; j++) {
#pragma unroll
        for (int pr = 0; pr < 2; pr++) {
            int y = row0 + pr;
            float4 v;
            v.x = fmaf(2.f, acc[pr][0][j], -sa[pr][0]) - sw[j];
            v.y = fmaf(2.f, acc[pr][1][j], -sa[pr][1]) - sw[j];
            v.z = fmaf(2.f, acc[pr][2][j], -sa[pr][2]) - sw[j];
            v.w = fmaf(2.f, acc[pr][3][j], -sa[pr][3]) - sw[j];
            *(float4*)&pbase[j * NPIX + y * 32 + x0] = v;
        }
    }
}

// ---------------- combine adder2 partials + channel means (vectorized) ---
__global__ void k_comb_se() {
    int bc  = blockIdx.x;   // 0..255 = b*64 + c
    int tid = threadIdx.x;  // 256 -> one quad each
    int pix0 = bc * NPIX + tid * 4;

    float4 v = make_float4(0.f, 0.f, 0.f, 0.f);
#pragma unroll
    for (int sp = 0; sp < S_; sp++) {
        float4 p = *(const float4*)&g_p2[sp * NB + pix0];
        v.x += p.x; v.y += p.y; v.z += p.z; v.w += p.w;
    }
    *(float4*)&g_out2[pix0] = v;
    float lsum = v.x + v.y + v.z + v.w;

#pragma unroll
    for (int off = 16; off; off >>= 1)
        lsum += __shfl_xor_sync(0xffffffffu, lsum, off);
    __shared__ float ws[8];
    if ((tid & 31) == 0) ws[tid >> 5] = lsum;
    __syncthreads();
    if (tid == 0) {
        float t = 0.f;
#pragma unroll
        for (int i = 0; i < 8; i++) t += ws[i];
        g_s[bc] = t * (1.f / 1024.f);
    }
}

// ---------------- final: SE gate (per-block) + out = out2*g + x ----------
__global__ void k_final(const float* __restrict__ x,
                        const float* __restrict__ f1w, const float* __restrict__ f1b,
                        const float* __restrict__ f2w, const float* __restrict__ f2b,
                        float* __restrict__ out) {
    int bc  = blockIdx.x;            // 0..255 = b*64 + c
    int b   = bc >> 6;
    int c   = bc & 63;
    int tid = threadIdx.x;           // 256

    __shared__ float sh[64];
    __shared__ float gg;
    if (tid < 64) sh[tid] = g_s[b * 64 + tid];
    __syncthreads();
    if (tid == 0) {
        float h[4];
#pragma unroll
        for (int j = 0; j < 4; j++) {
            float a = f1b[j];
            for (int c2 = 0; c2 < 64; c2++) a += sh[c2] * f1w[j * 64 + c2];
            h[j] = fmaxf(a, 0.f);
        }
        float z = f2b[c];
#pragma unroll
        for (int j = 0; j < 4; j++) z += h[j] * f2w[c * 4 + j];
        gg = 1.f / (1.f + expf(-z));
    }
    __syncthreads();
    float g = gg;
    int pix0 = bc * NPIX + tid * 4;
    float4 o2 = *(const float4*)&g_out2[pix0];
    float4 xs = *(const float4*)&x[pix0];
    float4 r;
    r.x = o2.x * g + xs.x; r.y = o2.y * g + xs.y;
    r.z = o2.z * g + xs.z; r.w = o2.w * g + xs.w;
    *(float4*)&out[pix0] = r;
}

extern "C" void kernel_launch(void* const* d_in, const int* in_sizes, int n_in,
                              void* d_out, int out_size) {
    const float* x     = (const float*)d_in[0];
    const float* bn1_g = (const float*)d_in[1];
    const float* bn1_b = (const float*)d_in[2];
    const float* bn1_m = (const float*)d_in[3];
    const float* bn1_v = (const float*)d_in[4];
    const float* w1    = (const float*)d_in[5];
    const float* bn2_g = (const float*)d_in[6];
    const float* bn2_b = (const float*)d_in[7];
    const float* bn2_m = (const float*)d_in[8];
    const float* bn2_v = (const float*)d_in[9];
    const float* w2    = (const float*)d_in[10];
    const float* fc1_w = (const float*)d_in[11];
    const float* fc1_b = (const float*)d_in[12];
    const float* fc2_w = (const float*)d_in[13];
    const float* fc2_b = (const float*)d_in[14];
    float* out = (float*)d_out;

    const int wtot   = 2 * S_ * KW_ * 64;
    const int bn_tot = B_ * C_ * 256 + NPAD;
    dim3 ag(64, S_);

    k_wprep<<<(wtot + 255) / 256, 256>>>(w1, w2);
    k_bnpad<<<(bn_tot + 255) / 256, 256>>>(x, 0, bn1_g, bn1_b, bn1_m, bn1_v);
    k_adder<<<ag, 128>>>(0);
    k_bnpad<<<(bn_tot + 255) / 256, 256>>>(nullptr, 1, bn2_g, bn2_b, bn2_m, bn2_v);
    k_adder<<<ag, 128>>>(1);
    k_comb_se<<<256, 256>>>();
    k_final<<<256, 256>>>(x, fc1_w, fc1_b, fc2_w, fc2_b, out);
}